// round 10
// baseline (speedup 1.0000x reference)
#include <cuda_runtime.h>
#include <cstdint>

// ParametricInterpolation — numerics FROZEN (bit-exact vs reference since R8):
//   p_k = RN(params_k * RN(1/fl32(scaler_k)))   (XLA divide->recip-mul)
//   i2 = RN(i*i), i3 = RN(i2*i), i4 = RN(i2*i2) (integer_pow sq-and-mul)
//   c  = RN(p0*i4); fma(p1,i3); fma(p2,i2); fma(p3,i); + p4  (ascending fma)
//   ci = rintf(c); k = c - ci; pos = clip(i - ci, 1, 2047)
//   out = RN(RN(x1*RN(1-k)) + RN(x2*k))          (non-contracted lerp)
//
// Perf change vs R9: persistent CTAs (1216 = 8/SM), each processing rows in a
// grid-stride loop with cp.async double-buffered smem staging. Next row's
// 8KB stage is in flight (LDGSTS, register-free) while the current row
// computes -> no wave transitions, memory pipe never drains.

#define SIG_LEN 2048
#define BATCH   16384
#define NCTAS   1216   // 152 SMs * 8 CTAs

__device__ __forceinline__ void cp_async16(uint32_t dst_smem, const void* src) {
    asm volatile("cp.async.cg.shared.global [%0], [%1], 16;"
                 :: "r"(dst_smem), "l"(src));
}
__device__ __forceinline__ void cp_commit() {
    asm volatile("cp.async.commit_group;");
}
template <int N>
__device__ __forceinline__ void cp_wait() {
    asm volatile("cp.async.wait_group %0;" :: "n"(N));
}

__global__ __launch_bounds__(256, 8)
void pik_kernel(const float* __restrict__ x,
                const float* __restrict__ params,
                float* __restrict__ out)
{
    __shared__ float sx[2][SIG_LEN];
    __shared__ float sp[2][5];

    const int tid = threadIdx.x;

    const uint32_t sx0 = (uint32_t)__cvta_generic_to_shared(&sx[0][0]);
    const uint32_t sx1 = (uint32_t)__cvta_generic_to_shared(&sx[1][0]);

    // fp32 correctly-rounded reciprocal of fl32(scaler[tid]) — XLA folded const.
    float inv = 1.0f;
    if (tid < 5) {
        inv = (tid == 0) ? (float)(1.0 / (double)1e12f) :
              (tid == 1) ? (float)(1.0 / (double)1e8f)  :
              (tid == 2) ? (float)(1.0 / (double)1e4f)  :
              (tid == 3) ? 1.0f :
                           (float)(1.0 / (double)10.0f);
    }

    const int row0 = blockIdx.x;

    // Prologue: stage first row into buffer 0.
    {
        const float4* src = reinterpret_cast<const float4*>(x + (size_t)row0 * SIG_LEN);
        cp_async16(sx0 + (uint32_t)tid * 16u,          src + tid);
        cp_async16(sx0 + (uint32_t)(tid + 256) * 16u,  src + tid + 256);
        cp_commit();
    }

    int it = 0;
    for (int row = row0; row < BATCH; row += NCTAS, ++it) {
        const int cur = it & 1;
        const uint32_t sx_nxt = (cur ? sx0 : sx1);

        const int nrow = row + NCTAS;
        const bool have_next = (nrow < BATCH);
        if (have_next) {
            const float4* src = reinterpret_cast<const float4*>(x + (size_t)nrow * SIG_LEN);
            cp_async16(sx_nxt + (uint32_t)tid * 16u,         src + tid);
            cp_async16(sx_nxt + (uint32_t)(tid + 256) * 16u, src + tid + 256);
            cp_commit();
            cp_wait<1>();   // current row's group done; next row's in flight
        } else {
            cp_wait<0>();
        }

        if (tid < 5)
            sp[cur][tid] = __fmul_rn(params[(size_t)row * 5 + tid], inv);
        __syncthreads();    // publish sx[cur] + sp[cur]

        const float p0 = sp[cur][0], p1 = sp[cur][1], p2 = sp[cur][2],
                    p3 = sp[cur][3], p4 = sp[cur][4];
        const float* sxc = sx[cur];
        float* orow = out + (size_t)row * SIG_LEN;

        #pragma unroll
        for (int part = 0; part < SIG_LEN / 256; ++part) {
            const int n = part * 256 + tid;
            const float fi = (float)n;

            const float i2 = __fmul_rn(fi, fi);   // exact
            const float i3 = __fmul_rn(i2, fi);
            const float i4 = __fmul_rn(i2, i2);

            float c = __fmul_rn(p0, i4);          // ascending-k fma chain
            c = __fmaf_rn(p1, i3, c);
            c = __fmaf_rn(p2, i2, c);
            c = __fmaf_rn(p3, fi, c);
            c = __fadd_rn(c, p4);

            const float ci = rintf(c);            // round half to even
            const float k  = __fadd_rn(c, -ci);

            float posf = fi - ci;                 // exact: integer-valued floats
            posf = fminf(fmaxf(posf, 1.0f), (float)(SIG_LEN - 1));
            const int pos = (int)posf;

            const float x1 = sxc[pos];            // warp-consecutive, conflict-free
            const float x2 = sxc[pos - 1];

            const float w1 = __fsub_rn(1.0f, k);  // non-contracted lerp
            orow[n] = __fadd_rn(__fmul_rn(x1, w1), __fmul_rn(x2, k));
        }
        __syncthreads();    // all reads of sx[cur] done before it is re-staged
    }
}

extern "C" void kernel_launch(void* const* d_in, const int* in_sizes, int n_in,
                              void* d_out, int out_size)
{
    const float* x;
    const float* params;
    if (n_in >= 2 && in_sizes[0] < in_sizes[1]) {
        params = (const float*)d_in[0];
        x      = (const float*)d_in[1];
    } else {
        x      = (const float*)d_in[0];
        params = (const float*)d_in[1];
    }
    float* out = (float*)d_out;

    pik_kernel<<<NCTAS, 256>>>(x, params, out);
}

// round 11
// speedup vs baseline: 1.1497x; 1.1497x over previous
#include <cuda_runtime.h>

// ParametricInterpolation — numerics FROZEN (bit-exact vs reference since R8):
//   p_k = RN(params_k * RN(1/fl32(scaler_k)))   (XLA divide->recip-mul)
//   i2 = RN(i*i), i3 = RN(i2*i), i4 = RN(i2*i2) (integer_pow sq-and-mul)
//   c  = RN(p0*i4); fma(p1,i3); fma(p2,i2); fma(p3,i); + p4  (ascending fma)
//   ci = rintf(c); k = c - ci; pos = clip(i - ci, 1, 2047)
//   out = RN(RN(x1*RN(1-k)) + RN(x2*k))          (non-contracted lerp)
//
// Perf change vs R9 (best): NO shared-memory staging. pos is warp-consecutive
// (round(curve) is near-constant across a warp), so the gathers are coalesced
// streaming LDGs; x[pos-1] hits L1 on x[pos]'s lines. Removes the STS/LDS
// round trip and the __syncthreads, and gives every thread 16 independent
// in-flight gather loads (8 parts x {x1,x2}).

#define SIG_LEN 2048

__global__ __launch_bounds__(256, 8)
void pik_kernel(const float* __restrict__ x,
                const float* __restrict__ params,
                float* __restrict__ out)
{
    const int b   = blockIdx.x;
    const int tid = threadIdx.x;

    // Per-thread param load; warp-uniform addresses -> broadcast, L1-resident.
    const float* pb = params + (size_t)b * 5;
    const float p0 = __fmul_rn(__ldg(pb + 0), (float)(1.0 / (double)1e12f));
    const float p1 = __fmul_rn(__ldg(pb + 1), (float)(1.0 / (double)1e8f));
    const float p2 = __fmul_rn(__ldg(pb + 2), (float)(1.0 / (double)1e4f));
    const float p3 =            __ldg(pb + 3);   // inv = 1.0 exactly
    const float p4 = __fmul_rn(__ldg(pb + 4), (float)(1.0 / (double)10.0f));

    const float* xrow = x   + (size_t)b * SIG_LEN;
    float*       orow = out + (size_t)b * SIG_LEN;

    int   pos[SIG_LEN / 256];
    float kk [SIG_LEN / 256];

    // Phase 1: compute all indices/weights (ALU only, no memory deps).
    #pragma unroll
    for (int part = 0; part < SIG_LEN / 256; ++part) {
        const int n = part * 256 + tid;
        const float fi = (float)n;

        const float i2 = __fmul_rn(fi, fi);   // exact
        const float i3 = __fmul_rn(i2, fi);
        const float i4 = __fmul_rn(i2, i2);

        float c = __fmul_rn(p0, i4);          // ascending-k fma chain
        c = __fmaf_rn(p1, i3, c);
        c = __fmaf_rn(p2, i2, c);
        c = __fmaf_rn(p3, fi, c);
        c = __fadd_rn(c, p4);

        const float ci = rintf(c);            // round half to even
        kk[part] = __fadd_rn(c, -ci);

        float posf = fi - ci;                 // exact: integer-valued floats
        posf = fminf(fmaxf(posf, 1.0f), (float)(SIG_LEN - 1));
        pos[part] = (int)posf;
    }

    // Phase 2: issue all gathers (16 independent LDGs in flight per thread).
    float x1v[SIG_LEN / 256], x2v[SIG_LEN / 256];
    #pragma unroll
    for (int part = 0; part < SIG_LEN / 256; ++part) {
        x1v[part] = __ldg(xrow + pos[part]);
        x2v[part] = __ldg(xrow + pos[part] - 1);
    }

    // Phase 3: lerp + coalesced stores.
    #pragma unroll
    for (int part = 0; part < SIG_LEN / 256; ++part) {
        const int n = part * 256 + tid;
        const float k  = kk[part];
        const float w1 = __fsub_rn(1.0f, k);  // non-contracted lerp
        orow[n] = __fadd_rn(__fmul_rn(x1v[part], w1), __fmul_rn(x2v[part], k));
    }
}

extern "C" void kernel_launch(void* const* d_in, const int* in_sizes, int n_in,
                              void* d_out, int out_size)
{
    const float* x;
    const float* params;
    if (n_in >= 2 && in_sizes[0] < in_sizes[1]) {
        params = (const float*)d_in[0];
        x      = (const float*)d_in[1];
    } else {
        x      = (const float*)d_in[0];
        params = (const float*)d_in[1];
    }
    float* out = (float*)d_out;

    const int batch = 16384;
    pik_kernel<<<batch, 256>>>(x, params, out);
}